// round 7
// baseline (speedup 1.0000x reference)
#include <cuda_runtime.h>
#include <math_constants.h>

// GraphPoolMol: masked neighborhood max-pool over graph Laplacian sparsity.
// B=64, MAX_ATOM=128, N_FEAT=128.
// out[b,i,f] = max_{j: L[b,i,j]!=0, j<n, i<n} x[b,j,f]; 0 if i>=n.
// diag(L)=1 => for i<n the neighbor set always contains j=i, so padding
// gather slots with the self row never changes the max, and mask==0 <=> i>=n.
//
// One warp owns TWO rows (i and i+64): 4096 warps total -> single wave.
// Row masks live as two 64-bit words; peel with ffsll (2 chains/row).

#define AT 128
#define NF 128
#define THREADS 256

__device__ __forceinline__ float4 fmax4(float4 a, float4 b) {
    return make_float4(fmaxf(a.x, b.x), fmaxf(a.y, b.y),
                       fmaxf(a.z, b.z), fmaxf(a.w, b.w));
}

// Mlo = (m1<<32)|m0 : bit p<32 -> col 4p,   p>=32 -> col 4(p-32)+1
__device__ __forceinline__ int col_lo(int p) { return ((p & 31) << 2) | (p >> 5); }
// Mhi = (m3<<32)|m2 : bit p<32 -> col 4p+2, p>=32 -> col 4(p-32)+3
__device__ __forceinline__ int col_hi(int p) { return ((p & 31) << 2) + 2 + (p >> 5); }

__global__ __launch_bounds__(THREADS, 4)
void graph_pool_mol_kernel(const float* __restrict__ xg,
                           const float* __restrict__ Lg,
                           const int* __restrict__ mol_slice,
                           float* __restrict__ outg)
{
    const int gw   = (blockIdx.x * THREADS + threadIdx.x) >> 5;
    const int lane = threadIdx.x & 31;
    const int b    = gw >> 6;            // batch
    const int w    = gw & 63;            // 0..63
    const int i0   = w;                  // first row
    const int i1   = w + 64;             // second row

    const int n = __ldg(mol_slice + 2 * b);       // n_atoms

    float4* outb = reinterpret_cast<float4*>(outg) + (size_t)b * AT * 32;
    const float4 zero = make_float4(0.f, 0.f, 0.f, 0.f);

    const bool v0 = (i0 < n);
    const bool v1 = (i1 < n);             // v1 => v0

    if (!v0) {                            // both rows padded: write zeros
        outb[(size_t)i0 * 32 + lane] = zero;
        outb[(size_t)i1 * 32 + lane] = zero;
        return;
    }

    // ---- Load L rows (coalesced float4/lane), build 64-bit masks ----------
    const float4* Lb4 = reinterpret_cast<const float4*>(Lg + (size_t)b * AT * AT);
    const float4 L0 = __ldg(Lb4 + (size_t)i0 * 32 + lane);
    float4 L1 = zero;
    if (v1) L1 = __ldg(Lb4 + (size_t)i1 * 32 + lane);

    const int j0 = 4 * lane;
    const bool c0 = (j0 + 0) < n, c1 = (j0 + 1) < n,
               c2 = (j0 + 2) < n, c3 = (j0 + 3) < n;

    const unsigned a_m0 = __ballot_sync(0xffffffffu, (L0.x != 0.f) && c0);
    const unsigned a_m1 = __ballot_sync(0xffffffffu, (L0.y != 0.f) && c1);
    const unsigned a_m2 = __ballot_sync(0xffffffffu, (L0.z != 0.f) && c2);
    const unsigned a_m3 = __ballot_sync(0xffffffffu, (L0.w != 0.f) && c3);
    const unsigned b_m0 = __ballot_sync(0xffffffffu, (L1.x != 0.f) && c0);
    const unsigned b_m1 = __ballot_sync(0xffffffffu, (L1.y != 0.f) && c1);
    const unsigned b_m2 = __ballot_sync(0xffffffffu, (L1.z != 0.f) && c2);
    const unsigned b_m3 = __ballot_sync(0xffffffffu, (L1.w != 0.f) && c3);

    unsigned long long Alo = ((unsigned long long)a_m1 << 32) | a_m0;
    unsigned long long Ahi = ((unsigned long long)a_m3 << 32) | a_m2;
    unsigned long long Blo = ((unsigned long long)b_m1 << 32) | b_m0;
    unsigned long long Bhi = ((unsigned long long)b_m3 << 32) | b_m2;

    const int kA = max(__popcll(Alo), __popcll(Ahi));   // >=1 (diag, v0)
    const int kB = max(__popcll(Blo), __popcll(Bhi));   // 0 iff !v1
    const int kmax = max(kA, kB);

    // ---- Gather: 4 independent chains over the row pair --------------------
    const float4* xb = reinterpret_cast<const float4*>(xg + (size_t)b * AT * NF);
    const float4 ninf = make_float4(-CUDART_INF_F, -CUDART_INF_F,
                                    -CUDART_INF_F, -CUDART_INF_F);
    float4 aa0 = ninf, aa1 = ninf, bb0 = ninf, bb1 = ninf;

    #pragma unroll 2
    for (int k = 0; k < kmax; ++k) {
        // Peel one index per chain; empty chain -> self row (harmless).
        int jA0 = i0, jA1 = i0, jB0 = i1, jB1 = i1;
        if (Alo) { const int p = __ffsll(Alo) - 1; jA0 = col_lo(p); Alo &= Alo - 1; }
        if (Ahi) { const int p = __ffsll(Ahi) - 1; jA1 = col_hi(p); Ahi &= Ahi - 1; }
        if (Blo) { const int p = __ffsll(Blo) - 1; jB0 = col_lo(p); Blo &= Blo - 1; }
        if (Bhi) { const int p = __ffsll(Bhi) - 1; jB1 = col_hi(p); Bhi &= Bhi - 1; }

        if (k < kA) {
            const float4 vA0 = __ldg(xb + (size_t)jA0 * 32 + lane);
            const float4 vA1 = __ldg(xb + (size_t)jA1 * 32 + lane);
            aa0 = fmax4(aa0, vA0);
            aa1 = fmax4(aa1, vA1);
        }
        if (k < kB) {
            const float4 vB0 = __ldg(xb + (size_t)jB0 * 32 + lane);
            const float4 vB1 = __ldg(xb + (size_t)jB1 * 32 + lane);
            bb0 = fmax4(bb0, vB0);
            bb1 = fmax4(bb1, vB1);
        }
    }

    outb[(size_t)i0 * 32 + lane] = fmax4(aa0, aa1);
    outb[(size_t)i1 * 32 + lane] = v1 ? fmax4(bb0, bb1) : zero;
}

extern "C" void kernel_launch(void* const* d_in, const int* in_sizes, int n_in,
                              void* d_out, int out_size)
{
    const float* node_features = (const float*)d_in[0];
    const float* laplacian     = (const float*)d_in[1];
    const int*   mol_slice     = (const int*)d_in[2];
    // d_in[3] = l_slice (unused)

    float* out = (float*)d_out;

    const int B = 64;
    const int total_warps = B * 64;               // 4096 warps, 2 rows each
    const int blocks = total_warps / (THREADS / 32);   // 512
    graph_pool_mol_kernel<<<blocks, THREADS>>>(
        node_features, laplacian, mol_slice, out);
}